// round 13
// baseline (speedup 1.0000x reference)
#include <cuda_runtime.h>
#include <cuda_bf16.h>
#include <cuda_fp16.h>
#include <cstdint>

// ===========================================================================
// GQA layer, sm_103 baseline-PTX path: mma.sync (HMMA) everywhere.
//   - prep: pure-streaming fp32->fp16 (weights keep [K,N] layout)
//   - ONE megakernel: QKV gemm + flash attention + O gemm, chained by
//     device counters (in-order CTA dispatch guarantees progress).
//   - GEMM B operands are K-major, loaded via ldmatrix.trans (flash-V pattern)
// ===========================================================================

#define S_LEN   2048
#define D_MODEL 2048
#define H_Q     32
#define KV_W    512
#define GK      2048
#define QSCALE  0.1803368801111244f   // 0.125 * log2(e)
#define ONES2   0x3C003C00u           // half2(1.0, 1.0)

// ------------------------------ scratch ------------------------------------
__device__ __align__(16) __half g_qh[S_LEN * D_MODEL];
__device__ __align__(16) __half g_kh[S_LEN * KV_W];
__device__ __align__(16) __half g_vh[S_LEN * KV_W];

__device__ __align__(16) __half g_ah[S_LEN * D_MODEL];
__device__ __align__(16) __half g_bh[S_LEN * D_MODEL];
__device__ __align__(16) __half g_ch[S_LEN * D_MODEL];

// weights fp16, native [K][N] layout
__device__ __align__(16) __half g_wq[GK * D_MODEL];
__device__ __align__(16) __half g_wk[GK * KV_W];
__device__ __align__(16) __half g_wv[GK * KV_W];
__device__ __align__(16) __half g_wo[GK * D_MODEL];

// dependency counters
__device__ int g_qflag[256];   // [qt*16 + bx]: Q-proj tile done
__device__ int g_kvcnt[16];    // per 128-row kv block: 8 CTAs (4 K + 4 V)
__device__ int g_ocnt[16];     // per qt: 32 flash CTAs done

// ------------------------------ helpers ------------------------------------
__device__ __forceinline__ uint32_t smem_u32(const void* p) {
    uint32_t a;
    asm("{ .reg .u64 t; cvta.to.shared.u64 t, %1; cvt.u32.u64 %0, t; }"
        : "=r"(a) : "l"(p));
    return a;
}

#define CP16(dst, src) \
    asm volatile("cp.async.cg.shared.global [%0], [%1], 16;" \
                 :: "r"(dst), "l"(src))
#define CPCOMMIT() asm volatile("cp.async.commit_group;" ::: "memory")
#define CPWAIT(n)  asm volatile("cp.async.wait_group %0;" :: "n"(n) : "memory")

__device__ __forceinline__ void ldsm_x4(uint32_t& r0, uint32_t& r1,
                                        uint32_t& r2, uint32_t& r3, uint32_t a) {
    asm volatile("ldmatrix.sync.aligned.m8n8.x4.shared.b16 {%0,%1,%2,%3}, [%4];"
                 : "=r"(r0), "=r"(r1), "=r"(r2), "=r"(r3) : "r"(a));
}
__device__ __forceinline__ void ldsm_x4t(uint32_t& r0, uint32_t& r1,
                                         uint32_t& r2, uint32_t& r3, uint32_t a) {
    asm volatile("ldmatrix.sync.aligned.m8n8.x4.trans.shared.b16 {%0,%1,%2,%3}, [%4];"
                 : "=r"(r0), "=r"(r1), "=r"(r2), "=r"(r3) : "r"(a));
}

__device__ __forceinline__ void mma_f16(float* c, const uint32_t* a,
                                        uint32_t b0, uint32_t b1) {
    asm volatile("mma.sync.aligned.m16n8k16.row.col.f32.f16.f16.f32 "
                 "{%0,%1,%2,%3}, {%4,%5,%6,%7}, {%8,%9}, {%0,%1,%2,%3};"
                 : "+f"(c[0]), "+f"(c[1]), "+f"(c[2]), "+f"(c[3])
                 : "r"(a[0]), "r"(a[1]), "r"(a[2]), "r"(a[3]), "r"(b0), "r"(b1));
}

__device__ __forceinline__ uint32_t h2exp2(uint32_t x) {
    uint32_t r;
    asm("ex2.approx.f16x2 %0, %1;" : "=r"(r) : "r"(x));
    return r;
}
__device__ __forceinline__ uint32_t packh2(float a, float b) {
    __half2 h = __floats2half2_rn(a, b);
    return *reinterpret_cast<uint32_t*>(&h);
}

__device__ __forceinline__ void kv_wait(int c) {
    volatile int* p = &g_kvcnt[c];
    while (*p < 8) __nanosleep(32);
}

// ---------------------------------------------------------------------------
// prep: pure streaming fp32 -> fp16 (7 tensors, z-indexed) + counter reset
// grid (64, 64, 7), 256 threads; each thread converts one float4
// ---------------------------------------------------------------------------
__global__ __launch_bounds__(256)
void prep(const float4* __restrict__ Wq, const float4* __restrict__ Wk,
          const float4* __restrict__ Wv, const float4* __restrict__ Wo,
          const float4* __restrict__ Qa, const float4* __restrict__ Ka,
          const float4* __restrict__ Va,
          __half* __restrict__ wq, __half* __restrict__ wk,
          __half* __restrict__ wv, __half* __restrict__ wo,
          __half* __restrict__ ah, __half* __restrict__ bh,
          __half* __restrict__ ch)
{
    if (blockIdx.x == 0 && blockIdx.y == 0 && blockIdx.z == 0) {
        if (threadIdx.x < 256) g_qflag[threadIdx.x] = 0;
        if (threadIdx.x < 16) { g_kvcnt[threadIdx.x] = 0; g_ocnt[threadIdx.x] = 0; }
    }

    const int z = blockIdx.z;
    const float4* A;  __half* dst;  int n4;
    if      (z == 0) { A = Wq; dst = wq; n4 = GK * D_MODEL / 4; }
    else if (z == 1) { A = Wk; dst = wk; n4 = GK * KV_W / 4; }
    else if (z == 2) { A = Wv; dst = wv; n4 = GK * KV_W / 4; }
    else if (z == 3) { A = Wo; dst = wo; n4 = GK * D_MODEL / 4; }
    else if (z == 4) { A = Qa; dst = ah; n4 = S_LEN * D_MODEL / 4; }
    else if (z == 5) { A = Ka; dst = bh; n4 = S_LEN * D_MODEL / 4; }
    else             { A = Va; dst = ch; n4 = S_LEN * D_MODEL / 4; }

    const int i = (blockIdx.y * 64 + blockIdx.x) * 256 + threadIdx.x;
    if (i >= n4) return;
    float4 v = A[i];
    __half2 h0 = __floats2half2_rn(v.x, v.y);
    __half2 h1 = __floats2half2_rn(v.z, v.w);
    uint2 u = make_uint2(*(uint32_t*)&h0, *(uint32_t*)&h1);
    *(uint2*)(dst + (size_t)i * 4) = u;
}

// ---------------------------------------------------------------------------
// GEMM body: C[128x128] = A @ B + bias.  A [M][GK] fp16 row-major;
// B [GK][NtotB] fp16 K-major (native weight layout), fragments via ldsm.trans.
// BK=64, 128 thr, 4 warps (2m x 2n), warp tile 64x64, 3-stage, 32KB/stage.
// Stage: A(16K) + B(two 64-col sub-tiles, 8K each).
// MODE 0: float out; MODE 1: half out; MODE 2: half out * QSCALE.
// ---------------------------------------------------------------------------
#define GSTAGE 32768

template <int MODE>
__device__ __forceinline__
void gemm_body(const __half* __restrict__ A, const __half* __restrict__ B,
               const float* __restrict__ bias, void* __restrict__ Cout,
               int Ntot, int NtotB, int m0, int n0, uint32_t sb)
{
    const int tid  = threadIdx.x;
    const int lane = tid & 31;
    const int wid  = tid >> 5;
    const int wm   = (wid & 1) * 64;
    const int wn   = (wid >> 1) * 64;
    const int gg   = lane >> 2, tg = lane & 3;
    const int mi   = lane >> 3;
    const uint32_t bsub = sb + 16384 + (wid >> 1) * 8192;

    float acc[4][8][4];
    #pragma unroll
    for (int a = 0; a < 4; a++)
        #pragma unroll
        for (int b = 0; b < 8; b++)
            #pragma unroll
            for (int c = 0; c < 4; c++) acc[a][b][c] = 0.f;

    auto load_stage = [&](int it) {
        const uint32_t st = sb + (it % 3) * GSTAGE;
        const int k0 = it * 64;
        // A: 128 rows x 128B (K-contig)
        #pragma unroll
        for (int t = 0; t < 8; t++) {
            const int f   = tid + t * 128;
            const int row = f >> 3, c = f & 7;
            CP16(st + row * 128 + ((c ^ (row & 7)) * 16),
                 A + (size_t)(m0 + row) * GK + k0 + c * 8);
        }
        // B: K-major, two sub-tiles of 64 k-rows x 128B (64 n-halves)
        #pragma unroll
        for (int t = 0; t < 8; t++) {
            const int f   = tid + t * 128;          // 0..1023
            const int sub = f >> 9;                 // n-half
            const int rem = f & 511;
            const int row = rem >> 3, c = rem & 7;  // k-row, 16B chunk
            CP16(st + 16384 + sub * 8192 + row * 128 + ((c ^ (row & 7)) * 16),
                 B + (size_t)(k0 + row) * NtotB + n0 + sub * 64 + c * 8);
        }
    };

    load_stage(0); CPCOMMIT();
    load_stage(1); CPCOMMIT();

    const int NIT = GK / 64;
    for (int it = 0; it < NIT; it++) {
        if (it + 1 < NIT) { CPWAIT(1); } else { CPWAIT(0); }
        __syncthreads();
        const uint32_t st = sb + (it % 3) * GSTAGE;
        const uint32_t bst = bsub + (it % 3) * GSTAGE;

        #pragma unroll
        for (int s = 0; s < 4; s++) {
            uint32_t aF[4][4];
            #pragma unroll
            for (int mt = 0; mt < 4; mt++) {
                const int r = wm + mt * 16 + (mi & 1) * 8 + (lane & 7);
                const int c = 2 * s + (mi >> 1);
                ldsm_x4(aF[mt][0], aF[mt][1], aF[mt][2], aF[mt][3],
                        st + r * 128 + ((c ^ (r & 7)) * 16));
            }
            uint32_t bF[8][2];
            #pragma unroll
            for (int nt = 0; nt < 4; nt++) {
                const int r = s * 16 + (mi & 1) * 8 + (lane & 7);
                const int c = 2 * nt + (mi >> 1);
                ldsm_x4t(bF[2*nt][0], bF[2*nt][1], bF[2*nt+1][0], bF[2*nt+1][1],
                         bst + r * 128 + ((c ^ (r & 7)) * 16));
            }
            #pragma unroll
            for (int mt = 0; mt < 4; mt++)
                #pragma unroll
                for (int n = 0; n < 8; n++)
                    mma_f16(acc[mt][n], aF[mt], bF[n][0], bF[n][1]);
        }
        if (it + 2 < NIT) { load_stage(it + 2); CPCOMMIT(); }
    }

    #pragma unroll
    for (int mt = 0; mt < 4; mt++)
        #pragma unroll
        for (int n = 0; n < 8; n++) {
            const int r0  = m0 + wm + mt * 16 + gg;
            const int col = n0 + wn + n * 8 + tg * 2;
            const float b0 = bias[col], b1 = bias[col + 1];
            if (MODE == 0) {
                float* C = (float*)Cout;
                *(float2*)(C + (size_t)r0 * Ntot + col) =
                    make_float2(acc[mt][n][0] + b0, acc[mt][n][1] + b1);
                *(float2*)(C + (size_t)(r0 + 8) * Ntot + col) =
                    make_float2(acc[mt][n][2] + b0, acc[mt][n][3] + b1);
            } else {
                const float sc = (MODE == 2) ? QSCALE : 1.0f;
                __half* C = (__half*)Cout;
                __half2 h0 = __floats2half2_rn((acc[mt][n][0] + b0) * sc,
                                               (acc[mt][n][1] + b1) * sc);
                __half2 h1 = __floats2half2_rn((acc[mt][n][2] + b0) * sc,
                                               (acc[mt][n][3] + b1) * sc);
                *(__half2*)(C + (size_t)r0 * Ntot + col) = h0;
                *(__half2*)(C + (size_t)(r0 + 8) * Ntot + col) = h1;
            }
        }
}

// ---------------------------------------------------------------------------
// flash body (math identical to R12)
// ---------------------------------------------------------------------------
__device__ __forceinline__
void flash_body(const __half* __restrict__ qbuf, const __half* __restrict__ kbuf,
                const __half* __restrict__ vbuf, __half* __restrict__ obuf,
                int qt, int h, char* smem)
{
    const uint32_t qb  = smem_u32(smem);
    const uint32_t kb0 = qb + 16384;
    const uint32_t vb0 = qb + 40960;

    const int g    = h >> 2;
    const int tid  = threadIdx.x;
    const int warp = tid >> 5, lane = tid & 31;
    const int gg   = lane >> 2, tg = lane & 3;
    const int mi   = lane >> 3;
    const int q0   = qt * 128;
    const int wrow = q0 + warp * 32;

    #pragma unroll
    for (int i = 0; i < 8; i++) {
        const int f = tid + i * 128;
        const int r = f >> 3, c = f & 7;
        CP16(qb + r * 128 + ((c ^ (r & 7)) * 16),
             qbuf + (size_t)(q0 + r) * D_MODEL + h * 64 + c * 8);
    }
    auto loadKV = [&](int kt) {
        kv_wait(kt >> 1);
        const uint32_t ko = kb0 + (kt % 3) * 8192;
        const uint32_t vo = vb0 + (kt % 3) * 8192;
        #pragma unroll
        for (int i = 0; i < 4; i++) {
            const int f = tid + i * 128;
            const int r = f >> 3, c = f & 7;
            const size_t src = (size_t)(kt * 64 + r) * KV_W + g * 64 + c * 8;
            const uint32_t d = r * 128 + ((c ^ (r & 7)) * 16);
            CP16(ko + d, kbuf + src);
            CP16(vo + d, vbuf + src);
        }
    };
    const int KT = 2 * qt + 2;
    loadKV(0); CPCOMMIT();
    if (KT > 1) loadKV(1);
    CPCOMMIT();
    CPWAIT(1);
    __syncthreads();

    uint32_t qa[4][2][4];
    #pragma unroll
    for (int mt = 0; mt < 2; mt++) {
        const int r = warp * 32 + mt * 16 + (mi & 1) * 8 + (lane & 7);
        #pragma unroll
        for (int s = 0; s < 4; s++) {
            const int c = 2 * s + (mi >> 1);
            ldsm_x4(qa[s][mt][0], qa[s][mt][1], qa[s][mt][2], qa[s][mt][3],
                    qb + r * 128 + ((c ^ (r & 7)) * 16));
        }
    }

    float o[2][8][4];
    #pragma unroll
    for (int mt = 0; mt < 2; mt++)
        #pragma unroll
        for (int n = 0; n < 8; n++)
            #pragma unroll
            for (int c = 0; c < 4; c++) o[mt][n][c] = 0.f;
    float mM[2][2] = {{-1e30f, -1e30f}, {-1e30f, -1e30f}};
    float lL[2][2] = {{0.f, 0.f}, {0.f, 0.f}};

    for (int kt = 0; kt < KT; kt++) {
        if (kt > 0) {
            if (kt + 1 < KT) { CPWAIT(1); } else { CPWAIT(0); }
            __syncthreads();
        }
        const uint32_t ko = kb0 + (kt % 3) * 8192;
        const uint32_t vo = vb0 + (kt % 3) * 8192;

        float sc[2][8][4];
        #pragma unroll
        for (int mt = 0; mt < 2; mt++)
            #pragma unroll
            for (int n = 0; n < 8; n++)
                #pragma unroll
                for (int c = 0; c < 4; c++) sc[mt][n][c] = 0.f;

        #pragma unroll
        for (int s = 0; s < 4; s++) {
            uint32_t bfr[8][2];
            #pragma unroll
            for (int nt = 0; nt < 4; nt++) {
                const int r = nt * 16 + (mi >> 1) * 8 + (lane & 7);
                const int c = 2 * s + (mi & 1);
                ldsm_x4(bfr[2*nt][0], bfr[2*nt][1], bfr[2*nt+1][0], bfr[2*nt+1][1],
                        ko + r * 128 + ((c ^ (r & 7)) * 16));
            }
            #pragma unroll
            for (int mt = 0; mt < 2; mt++)
                #pragma unroll
                for (int n = 0; n < 8; n++)
                    mma_f16(sc[mt][n], qa[s][mt], bfr[n][0], bfr[n][1]);
        }

        uint32_t vf0[8][2];
        #pragma unroll
        for (int nt = 0; nt < 4; nt++) {
            const int r = (mi & 1) * 8 + (lane & 7);
            const int c = 2 * nt + (mi >> 1);
            ldsm_x4t(vf0[2*nt][0], vf0[2*nt][1], vf0[2*nt+1][0], vf0[2*nt+1][1],
                     vo + r * 128 + ((c ^ (r & 7)) * 16));
        }

        if (kt * 64 + 63 > wrow) {
            #pragma unroll
            for (int mt = 0; mt < 2; mt++) {
                const int r0 = wrow + mt * 16 + gg;
                const int r1 = r0 + 8;
                #pragma unroll
                for (int n = 0; n < 8; n++) {
                    const int col = kt * 64 + n * 8 + tg * 2;
                    if (col     > r0) sc[mt][n][0] = -1e30f;
                    if (col + 1 > r0) sc[mt][n][1] = -1e30f;
                    if (col     > r1) sc[mt][n][2] = -1e30f;
                    if (col + 1 > r1) sc[mt][n][3] = -1e30f;
                }
            }
        }

        uint32_t pa[2][4][4];
        #pragma unroll
        for (int mt = 0; mt < 2; mt++) {
            float mx0 = -1e30f, mx1 = -1e30f;
            #pragma unroll
            for (int n = 0; n < 8; n++) {
                mx0 = fmaxf(mx0, fmaxf(sc[mt][n][0], sc[mt][n][1]));
                mx1 = fmaxf(mx1, fmaxf(sc[mt][n][2], sc[mt][n][3]));
            }
            mx0 = fmaxf(mx0, __shfl_xor_sync(0xffffffffu, mx0, 1));
            mx0 = fmaxf(mx0, __shfl_xor_sync(0xffffffffu, mx0, 2));
            mx1 = fmaxf(mx1, __shfl_xor_sync(0xffffffffu, mx1, 1));
            mx1 = fmaxf(mx1, __shfl_xor_sync(0xffffffffu, mx1, 2));
            const float mn0 = fmaxf(mM[mt][0], mx0);
            const float mn1 = fmaxf(mM[mt][1], mx1);
            const float c0 = exp2f(mM[mt][0] - mn0);
            const float c1 = exp2f(mM[mt][1] - mn1);
            mM[mt][0] = mn0; mM[mt][1] = mn1;

            #pragma unroll
            for (int s = 0; s < 4; s++) {
                pa[mt][s][0] = h2exp2(packh2(sc[mt][2*s][0]   - mn0, sc[mt][2*s][1]   - mn0));
                pa[mt][s][1] = h2exp2(packh2(sc[mt][2*s][2]   - mn1, sc[mt][2*s][3]   - mn1));
                pa[mt][s][2] = h2exp2(packh2(sc[mt][2*s+1][0] - mn0, sc[mt][2*s+1][1] - mn0));
                pa[mt][s][3] = h2exp2(packh2(sc[mt][2*s+1][2] - mn1, sc[mt][2*s+1][3] - mn1));
            }

            float lacc[4] = {0.f, 0.f, 0.f, 0.f};
            #pragma unroll
            for (int s = 0; s < 4; s++)
                mma_f16(lacc, pa[mt][s], ONES2, ONES2);
            lL[mt][0] = lL[mt][0] * c0 + lacc[0];
            lL[mt][1] = lL[mt][1] * c1 + lacc[2];

            #pragma unroll
            for (int n = 0; n < 8; n++) {
                o[mt][n][0] *= c0; o[mt][n][1] *= c0;
                o[mt][n][2] *= c1; o[mt][n][3] *= c1;
            }
        }

        #pragma unroll
        for (int mt = 0; mt < 2; mt++)
            #pragma unroll
            for (int n = 0; n < 8; n++)
                mma_f16(o[mt][n], pa[mt][0], vf0[n][0], vf0[n][1]);

        #pragma unroll
        for (int s = 1; s < 4; s++) {
            uint32_t vfr[8][2];
            #pragma unroll
            for (int nt = 0; nt < 4; nt++) {
                const int r = s * 16 + (mi & 1) * 8 + (lane & 7);
                const int c = 2 * nt + (mi >> 1);
                ldsm_x4t(vfr[2*nt][0], vfr[2*nt][1], vfr[2*nt+1][0], vfr[2*nt+1][1],
                         vo + r * 128 + ((c ^ (r & 7)) * 16));
            }
            #pragma unroll
            for (int mt = 0; mt < 2; mt++)
                #pragma unroll
                for (int n = 0; n < 8; n++)
                    mma_f16(o[mt][n], pa[mt][s], vfr[n][0], vfr[n][1]);
        }

        if (kt + 2 < KT) { loadKV(kt + 2); CPCOMMIT(); }
    }

    #pragma unroll
    for (int mt = 0; mt < 2; mt++) {
        const float i0 = 1.f / lL[mt][0], i1 = 1.f / lL[mt][1];
        const int r0 = wrow + mt * 16 + gg;
        const int r1 = r0 + 8;
        #pragma unroll
        for (int n = 0; n < 8; n++) {
            const int col = h * 64 + n * 8 + tg * 2;
            *(uint32_t*)(obuf + (size_t)r0 * D_MODEL + col) =
                packh2(o[mt][n][0] * i0, o[mt][n][1] * i0);
            *(uint32_t*)(obuf + (size_t)r1 * D_MODEL + col) =
                packh2(o[mt][n][2] * i1, o[mt][n][3] * i1);
        }
    }
}

// ---------------------------------------------------------------------------
// megakernel: grid = 1152 x 128 threads
//   bid   0..383 : QKV gemm (bx=bid%24, by=bid/24); posts qflag / kvcnt
//   bid 384..895 : flash (qt = 15 - (f>>5) longest-first, h = f&31);
//                  spins on qflag + incremental kvcnt; posts ocnt
//   bid 896..1151: O gemm tile; spins on ocnt[qi]
// ---------------------------------------------------------------------------
__global__ __launch_bounds__(128, 2)
void mega(const __half* __restrict__ Qa, const __half* __restrict__ Ka,
          const __half* __restrict__ Va,
          const __half* __restrict__ WQ, const __half* __restrict__ WK,
          const __half* __restrict__ WV, const __half* __restrict__ WO,
          const float* __restrict__ bq, const float* __restrict__ bk,
          const float* __restrict__ bv, const float* __restrict__ bo,
          __half* __restrict__ qh, __half* __restrict__ kh,
          __half* __restrict__ vh, __half* __restrict__ abuf,
          float* __restrict__ out)
{
    extern __shared__ char sm[];
    const uint32_t sb = smem_u32(sm);
    const int bid = blockIdx.x;

    if (bid < 384) {
        const int bx = bid % 24;
        const int by = bid / 24;
        const int m0 = by * 128;
        if (bx < 16) {
            gemm_body<2>(Qa, WQ, bq, qh, D_MODEL, D_MODEL, m0, bx * 128, sb);
            __syncthreads();
            if (threadIdx.x == 0) {
                __threadfence();
                atomicExch(&g_qflag[by * 16 + bx], 1);
            }
        } else if (bx < 20) {
            gemm_body<1>(Ka, WK, bk, kh, KV_W, KV_W, m0, (bx - 16) * 128, sb);
            __syncthreads();
            if (threadIdx.x == 0) {
                __threadfence();
                atomicAdd(&g_kvcnt[by], 1);
            }
        } else {
            gemm_body<1>(Va, WV, bv, vh, KV_W, KV_W, m0, (bx - 20) * 128, sb);
            __syncthreads();
            if (threadIdx.x == 0) {
                __threadfence();
                atomicAdd(&g_kvcnt[by], 1);
            }
        }
    } else if (bid < 896) {
        const int f  = bid - 384;
        const int qt = 15 - (f >> 5);
        const int h  = f & 31;
        {   // wait for our Q tile (all threads, broadcast load)
            volatile int* qf = &g_qflag[qt * 16 + (h >> 1)];
            while (*qf == 0) __nanosleep(32);
        }
        flash_body(qh, kh, vh, abuf, qt, h, sm);
        __syncthreads();
        if (threadIdx.x == 0) {
            __threadfence();
            atomicAdd(&g_ocnt[qt], 1);
        }
    } else {
        const int t  = bid - 896;
        const int qi = t >> 4;
        const int n0 = (t & 15) * 128;
        if (threadIdx.x == 0) {
            while (atomicAdd(&g_ocnt[qi], 0) < 32)
                __nanosleep(64);
        }
        __syncthreads();
        __threadfence();
        gemm_body<0>(abuf, WO, bo, out, D_MODEL, D_MODEL, qi * 128, n0, sb);
    }
}

// ---------------------------------------------------------------------------
// Launch
// ---------------------------------------------------------------------------
extern "C" void kernel_launch(void* const* d_in, const int* in_sizes, int n_in,
                              void* d_out, int out_size)
{
    const float* queries = (const float*)d_in[0];
    const float* keys    = (const float*)d_in[1];
    const float* values  = (const float*)d_in[2];
    const float* Wq      = (const float*)d_in[3];
    const float* bq      = (const float*)d_in[4];
    const float* Wk      = (const float*)d_in[5];
    const float* bk      = (const float*)d_in[6];
    const float* Wv      = (const float*)d_in[7];
    const float* bv      = (const float*)d_in[8];
    const float* Wo      = (const float*)d_in[9];
    const float* bo      = (const float*)d_in[10];
    float*       out     = (float*)d_out;

    __half *qh, *kh, *vh, *ah, *bh, *ch, *wq, *wk, *wv, *wo;
    cudaGetSymbolAddress((void**)&qh, g_qh);
    cudaGetSymbolAddress((void**)&kh, g_kh);
    cudaGetSymbolAddress((void**)&vh, g_vh);
    cudaGetSymbolAddress((void**)&ah, g_ah);
    cudaGetSymbolAddress((void**)&bh, g_bh);
    cudaGetSymbolAddress((void**)&ch, g_ch);
    cudaGetSymbolAddress((void**)&wq, g_wq);
    cudaGetSymbolAddress((void**)&wk, g_wk);
    cudaGetSymbolAddress((void**)&wv, g_wv);
    cudaGetSymbolAddress((void**)&wo, g_wo);

    cudaFuncSetAttribute(mega, cudaFuncAttributeMaxDynamicSharedMemorySize, 3 * GSTAGE);

    // streaming prep (weights keep [K,N] layout) + counter reset
    prep<<<dim3(64, 64, 7), 256>>>(
        (const float4*)Wq, (const float4*)Wk, (const float4*)Wv, (const float4*)Wo,
        (const float4*)queries, (const float4*)keys, (const float4*)values,
        wq, wk, wv, wo, ah, bh, ch);

    // everything else in one launch
    mega<<<1152, 128, 3 * GSTAGE>>>(
        ah, bh, ch, wq, wk, wv, wo, bq, bk, bv, bo,
        qh, kh, vh, ah, out);
}

// round 14
// speedup vs baseline: 1.0373x; 1.0373x over previous
#include <cuda_runtime.h>
#include <cuda_bf16.h>
#include <cuda_fp16.h>
#include <cstdint>

// ===========================================================================
// GQA layer, sm_103 baseline-PTX path: mma.sync (HMMA) everywhere.
//   - prep: pure-streaming fp32->fp16 (weights keep native [K,N] layout)
//   - gemm_qkv: fused Q/K/V projections (K-major B via ldsm.trans)
//   - flash_o: flash attention + O-projection fused via per-qt counters
// ===========================================================================

#define S_LEN   2048
#define D_MODEL 2048
#define H_Q     32
#define KV_W    512
#define GK      2048
#define QSCALE  0.1803368801111244f   // 0.125 * log2(e)
#define ONES2   0x3C003C00u           // half2(1.0, 1.0)

// ------------------------------ scratch ------------------------------------
__device__ __align__(16) __half g_qh[S_LEN * D_MODEL];
__device__ __align__(16) __half g_kh[S_LEN * KV_W];
__device__ __align__(16) __half g_vh[S_LEN * KV_W];

__device__ __align__(16) __half g_ah[S_LEN * D_MODEL];
__device__ __align__(16) __half g_bh[S_LEN * D_MODEL];
__device__ __align__(16) __half g_ch[S_LEN * D_MODEL];

// weights fp16, native [K][N] layout
__device__ __align__(16) __half g_wq[GK * D_MODEL];
__device__ __align__(16) __half g_wk[GK * KV_W];
__device__ __align__(16) __half g_wv[GK * KV_W];
__device__ __align__(16) __half g_wo[GK * D_MODEL];

__device__ int g_ocnt[16];    // per qt: 32 flash CTAs done

// ------------------------------ helpers ------------------------------------
__device__ __forceinline__ uint32_t smem_u32(const void* p) {
    uint32_t a;
    asm("{ .reg .u64 t; cvta.to.shared.u64 t, %1; cvt.u32.u64 %0, t; }"
        : "=r"(a) : "l"(p));
    return a;
}

#define CP16(dst, src) \
    asm volatile("cp.async.cg.shared.global [%0], [%1], 16;" \
                 :: "r"(dst), "l"(src))
#define CPCOMMIT() asm volatile("cp.async.commit_group;" ::: "memory")
#define CPWAIT(n)  asm volatile("cp.async.wait_group %0;" :: "n"(n) : "memory")

__device__ __forceinline__ void ldsm_x4(uint32_t& r0, uint32_t& r1,
                                        uint32_t& r2, uint32_t& r3, uint32_t a) {
    asm volatile("ldmatrix.sync.aligned.m8n8.x4.shared.b16 {%0,%1,%2,%3}, [%4];"
                 : "=r"(r0), "=r"(r1), "=r"(r2), "=r"(r3) : "r"(a));
}
__device__ __forceinline__ void ldsm_x4t(uint32_t& r0, uint32_t& r1,
                                         uint32_t& r2, uint32_t& r3, uint32_t a) {
    asm volatile("ldmatrix.sync.aligned.m8n8.x4.trans.shared.b16 {%0,%1,%2,%3}, [%4];"
                 : "=r"(r0), "=r"(r1), "=r"(r2), "=r"(r3) : "r"(a));
}

__device__ __forceinline__ void mma_f16(float* c, const uint32_t* a,
                                        uint32_t b0, uint32_t b1) {
    asm volatile("mma.sync.aligned.m16n8k16.row.col.f32.f16.f16.f32 "
                 "{%0,%1,%2,%3}, {%4,%5,%6,%7}, {%8,%9}, {%0,%1,%2,%3};"
                 : "+f"(c[0]), "+f"(c[1]), "+f"(c[2]), "+f"(c[3])
                 : "r"(a[0]), "r"(a[1]), "r"(a[2]), "r"(a[3]), "r"(b0), "r"(b1));
}

__device__ __forceinline__ uint32_t h2exp2(uint32_t x) {
    uint32_t r;
    asm("ex2.approx.f16x2 %0, %1;" : "=r"(r) : "r"(x));
    return r;
}
__device__ __forceinline__ uint32_t packh2(float a, float b) {
    __half2 h = __floats2half2_rn(a, b);
    return *reinterpret_cast<uint32_t*>(&h);
}

// ---------------------------------------------------------------------------
// prep: pure streaming fp32 -> fp16 (7 tensors, z-indexed) + counter reset
// ---------------------------------------------------------------------------
__global__ __launch_bounds__(256)
void prep(const float4* __restrict__ Wq, const float4* __restrict__ Wk,
          const float4* __restrict__ Wv, const float4* __restrict__ Wo,
          const float4* __restrict__ Qa, const float4* __restrict__ Ka,
          const float4* __restrict__ Va,
          __half* __restrict__ wq, __half* __restrict__ wk,
          __half* __restrict__ wv, __half* __restrict__ wo,
          __half* __restrict__ ah, __half* __restrict__ bh,
          __half* __restrict__ ch)
{
    if (blockIdx.x == 0 && blockIdx.y == 0 && blockIdx.z == 0 &&
        threadIdx.x < 16)
        g_ocnt[threadIdx.x] = 0;

    const int z = blockIdx.z;
    const float4* A;  __half* dst;  int n4;
    if      (z == 0) { A = Wq; dst = wq; n4 = GK * D_MODEL / 4; }
    else if (z == 1) { A = Wk; dst = wk; n4 = GK * KV_W / 4; }
    else if (z == 2) { A = Wv; dst = wv; n4 = GK * KV_W / 4; }
    else if (z == 3) { A = Wo; dst = wo; n4 = GK * D_MODEL / 4; }
    else if (z == 4) { A = Qa; dst = ah; n4 = S_LEN * D_MODEL / 4; }
    else if (z == 5) { A = Ka; dst = bh; n4 = S_LEN * D_MODEL / 4; }
    else             { A = Va; dst = ch; n4 = S_LEN * D_MODEL / 4; }

    const int i = (blockIdx.y * 64 + blockIdx.x) * 256 + threadIdx.x;
    if (i >= n4) return;
    float4 v = A[i];
    __half2 h0 = __floats2half2_rn(v.x, v.y);
    __half2 h1 = __floats2half2_rn(v.z, v.w);
    uint2 u = make_uint2(*(uint32_t*)&h0, *(uint32_t*)&h1);
    *(uint2*)(dst + (size_t)i * 4) = u;
}

// ---------------------------------------------------------------------------
// GEMM body: C[128x128] = A @ B + bias.  A [M][GK] fp16 row-major;
// B [GK][NtotB] fp16 K-major (native weight layout), fragments via ldsm.trans.
// BK=64, 128 thr, 4 warps (2m x 2n), warp tile 64x64, 3-stage, 32KB/stage.
// MODE 0: float out; MODE 1: half out; MODE 2: half out * QSCALE.
// ---------------------------------------------------------------------------
#define GSTAGE 32768

template <int MODE>
__device__ __forceinline__
void gemm_body(const __half* __restrict__ A, const __half* __restrict__ B,
               const float* __restrict__ bias, void* __restrict__ Cout,
               int Ntot, int NtotB, int m0, int n0, uint32_t sb)
{
    const int tid  = threadIdx.x;
    const int lane = tid & 31;
    const int wid  = tid >> 5;
    const int wm   = (wid & 1) * 64;
    const int wn   = (wid >> 1) * 64;
    const int gg   = lane >> 2, tg = lane & 3;
    const int mi   = lane >> 3;
    const uint32_t bsub = sb + 16384 + (wid >> 1) * 8192;

    float acc[4][8][4];
    #pragma unroll
    for (int a = 0; a < 4; a++)
        #pragma unroll
        for (int b = 0; b < 8; b++)
            #pragma unroll
            for (int c = 0; c < 4; c++) acc[a][b][c] = 0.f;

    auto load_stage = [&](int it) {
        const uint32_t st = sb + (it % 3) * GSTAGE;
        const int k0 = it * 64;
        // A: 128 rows x 128B (K-contig)
        #pragma unroll
        for (int t = 0; t < 8; t++) {
            const int f   = tid + t * 128;
            const int row = f >> 3, c = f & 7;
            CP16(st + row * 128 + ((c ^ (row & 7)) * 16),
                 A + (size_t)(m0 + row) * GK + k0 + c * 8);
        }
        // B: K-major, two sub-tiles of 64 k-rows x 128B (64 n-halves)
        #pragma unroll
        for (int t = 0; t < 8; t++) {
            const int f   = tid + t * 128;
            const int sub = f >> 9;
            const int rem = f & 511;
            const int row = rem >> 3, c = rem & 7;
            CP16(st + 16384 + sub * 8192 + row * 128 + ((c ^ (row & 7)) * 16),
                 B + (size_t)(k0 + row) * NtotB + n0 + sub * 64 + c * 8);
        }
    };

    load_stage(0); CPCOMMIT();
    load_stage(1); CPCOMMIT();

    const int NIT = GK / 64;
    for (int it = 0; it < NIT; it++) {
        if (it + 1 < NIT) { CPWAIT(1); } else { CPWAIT(0); }
        __syncthreads();
        const uint32_t st  = sb + (it % 3) * GSTAGE;
        const uint32_t bst = bsub + (it % 3) * GSTAGE;

        #pragma unroll
        for (int s = 0; s < 4; s++) {
            uint32_t aF[4][4];
            #pragma unroll
            for (int mt = 0; mt < 4; mt++) {
                const int r = wm + mt * 16 + (mi & 1) * 8 + (lane & 7);
                const int c = 2 * s + (mi >> 1);
                ldsm_x4(aF[mt][0], aF[mt][1], aF[mt][2], aF[mt][3],
                        st + r * 128 + ((c ^ (r & 7)) * 16));
            }
            uint32_t bF[8][2];
            #pragma unroll
            for (int nt = 0; nt < 4; nt++) {
                const int r = s * 16 + (mi & 1) * 8 + (lane & 7);
                const int c = 2 * nt + (mi >> 1);
                ldsm_x4t(bF[2*nt][0], bF[2*nt][1], bF[2*nt+1][0], bF[2*nt+1][1],
                         bst + r * 128 + ((c ^ (r & 7)) * 16));
            }
            #pragma unroll
            for (int mt = 0; mt < 4; mt++)
                #pragma unroll
                for (int n = 0; n < 8; n++)
                    mma_f16(acc[mt][n], aF[mt], bF[n][0], bF[n][1]);
        }
        if (it + 2 < NIT) { load_stage(it + 2); CPCOMMIT(); }
    }

    #pragma unroll
    for (int mt = 0; mt < 4; mt++)
        #pragma unroll
        for (int n = 0; n < 8; n++) {
            const int r0  = m0 + wm + mt * 16 + gg;
            const int col = n0 + wn + n * 8 + tg * 2;
            const float b0 = bias[col], b1 = bias[col + 1];
            if (MODE == 0) {
                float* C = (float*)Cout;
                *(float2*)(C + (size_t)r0 * Ntot + col) =
                    make_float2(acc[mt][n][0] + b0, acc[mt][n][1] + b1);
                *(float2*)(C + (size_t)(r0 + 8) * Ntot + col) =
                    make_float2(acc[mt][n][2] + b0, acc[mt][n][3] + b1);
            } else {
                const float sc = (MODE == 2) ? QSCALE : 1.0f;
                __half* C = (__half*)Cout;
                __half2 h0 = __floats2half2_rn((acc[mt][n][0] + b0) * sc,
                                               (acc[mt][n][1] + b1) * sc);
                __half2 h1 = __floats2half2_rn((acc[mt][n][2] + b0) * sc,
                                               (acc[mt][n][3] + b1) * sc);
                *(__half2*)(C + (size_t)r0 * Ntot + col) = h0;
                *(__half2*)(C + (size_t)(r0 + 8) * Ntot + col) = h1;
            }
        }
}

// fused Q + K + V projections: grid (24, 16)
__global__ __launch_bounds__(128, 2)
void gemm_qkv(const __half* __restrict__ Qa, const __half* __restrict__ Ka,
              const __half* __restrict__ Va,
              const __half* __restrict__ WQ, const __half* __restrict__ WK,
              const __half* __restrict__ WV,
              const float* __restrict__ bq, const float* __restrict__ bk,
              const float* __restrict__ bv,
              __half* __restrict__ qh, __half* __restrict__ kh, __half* __restrict__ vh)
{
    extern __shared__ char sm[];
    const uint32_t sb = smem_u32(sm);
    const int bx = blockIdx.x;
    const int m0 = blockIdx.y * 128;
    if (bx < 16)
        gemm_body<2>(Qa, WQ, bq, qh, D_MODEL, D_MODEL, m0, bx * 128, sb);
    else if (bx < 20)
        gemm_body<1>(Ka, WK, bk, kh, KV_W, KV_W, m0, (bx - 16) * 128, sb);
    else
        gemm_body<1>(Va, WV, bv, vh, KV_W, KV_W, m0, (bx - 20) * 128, sb);
}

// ---------------------------------------------------------------------------
// flash body (math identical to R12/R13)
// ---------------------------------------------------------------------------
__device__ __forceinline__
void flash_body(const __half* __restrict__ qbuf, const __half* __restrict__ kbuf,
                const __half* __restrict__ vbuf, __half* __restrict__ obuf,
                int qt, int h, char* smem)
{
    const uint32_t qb  = smem_u32(smem);
    const uint32_t kb0 = qb + 16384;
    const uint32_t vb0 = qb + 40960;

    const int g    = h >> 2;
    const int tid  = threadIdx.x;
    const int warp = tid >> 5, lane = tid & 31;
    const int gg   = lane >> 2, tg = lane & 3;
    const int mi   = lane >> 3;
    const int q0   = qt * 128;
    const int wrow = q0 + warp * 32;

    #pragma unroll
    for (int i = 0; i < 8; i++) {
        const int f = tid + i * 128;
        const int r = f >> 3, c = f & 7;
        CP16(qb + r * 128 + ((c ^ (r & 7)) * 16),
             qbuf + (size_t)(q0 + r) * D_MODEL + h * 64 + c * 8);
    }
    auto loadKV = [&](int kt) {
        const uint32_t ko = kb0 + (kt % 3) * 8192;
        const uint32_t vo = vb0 + (kt % 3) * 8192;
        #pragma unroll
        for (int i = 0; i < 4; i++) {
            const int f = tid + i * 128;
            const int r = f >> 3, c = f & 7;
            const size_t src = (size_t)(kt * 64 + r) * KV_W + g * 64 + c * 8;
            const uint32_t d = r * 128 + ((c ^ (r & 7)) * 16);
            CP16(ko + d, kbuf + src);
            CP16(vo + d, vbuf + src);
        }
    };
    const int KT = 2 * qt + 2;
    loadKV(0); CPCOMMIT();
    if (KT > 1) loadKV(1);
    CPCOMMIT();
    CPWAIT(1);
    __syncthreads();

    uint32_t qa[4][2][4];
    #pragma unroll
    for (int mt = 0; mt < 2; mt++) {
        const int r = warp * 32 + mt * 16 + (mi & 1) * 8 + (lane & 7);
        #pragma unroll
        for (int s = 0; s < 4; s++) {
            const int c = 2 * s + (mi >> 1);
            ldsm_x4(qa[s][mt][0], qa[s][mt][1], qa[s][mt][2], qa[s][mt][3],
                    qb + r * 128 + ((c ^ (r & 7)) * 16));
        }
    }

    float o[2][8][4];
    #pragma unroll
    for (int mt = 0; mt < 2; mt++)
        #pragma unroll
        for (int n = 0; n < 8; n++)
            #pragma unroll
            for (int c = 0; c < 4; c++) o[mt][n][c] = 0.f;
    float mM[2][2] = {{-1e30f, -1e30f}, {-1e30f, -1e30f}};
    float lL[2][2] = {{0.f, 0.f}, {0.f, 0.f}};

    for (int kt = 0; kt < KT; kt++) {
        if (kt > 0) {
            if (kt + 1 < KT) { CPWAIT(1); } else { CPWAIT(0); }
            __syncthreads();
        }
        const uint32_t ko = kb0 + (kt % 3) * 8192;
        const uint32_t vo = vb0 + (kt % 3) * 8192;

        float sc[2][8][4];
        #pragma unroll
        for (int mt = 0; mt < 2; mt++)
            #pragma unroll
            for (int n = 0; n < 8; n++)
                #pragma unroll
                for (int c = 0; c < 4; c++) sc[mt][n][c] = 0.f;

        #pragma unroll
        for (int s = 0; s < 4; s++) {
            uint32_t bfr[8][2];
            #pragma unroll
            for (int nt = 0; nt < 4; nt++) {
                const int r = nt * 16 + (mi >> 1) * 8 + (lane & 7);
                const int c = 2 * s + (mi & 1);
                ldsm_x4(bfr[2*nt][0], bfr[2*nt][1], bfr[2*nt+1][0], bfr[2*nt+1][1],
                        ko + r * 128 + ((c ^ (r & 7)) * 16));
            }
            #pragma unroll
            for (int mt = 0; mt < 2; mt++)
                #pragma unroll
                for (int n = 0; n < 8; n++)
                    mma_f16(sc[mt][n], qa[s][mt], bfr[n][0], bfr[n][1]);
        }

        uint32_t vf0[8][2];
        #pragma unroll
        for (int nt = 0; nt < 4; nt++) {
            const int r = (mi & 1) * 8 + (lane & 7);
            const int c = 2 * nt + (mi >> 1);
            ldsm_x4t(vf0[2*nt][0], vf0[2*nt][1], vf0[2*nt+1][0], vf0[2*nt+1][1],
                     vo + r * 128 + ((c ^ (r & 7)) * 16));
        }

        if (kt * 64 + 63 > wrow) {
            #pragma unroll
            for (int mt = 0; mt < 2; mt++) {
                const int r0 = wrow + mt * 16 + gg;
                const int r1 = r0 + 8;
                #pragma unroll
                for (int n = 0; n < 8; n++) {
                    const int col = kt * 64 + n * 8 + tg * 2;
                    if (col     > r0) sc[mt][n][0] = -1e30f;
                    if (col + 1 > r0) sc[mt][n][1] = -1e30f;
                    if (col     > r1) sc[mt][n][2] = -1e30f;
                    if (col + 1 > r1) sc[mt][n][3] = -1e30f;
                }
            }
        }

        uint32_t pa[2][4][4];
        #pragma unroll
        for (int mt = 0; mt < 2; mt++) {
            float mx0 = -1e30f, mx1 = -1e30f;
            #pragma unroll
            for (int n = 0; n < 8; n++) {
                mx0 = fmaxf(mx0, fmaxf(sc[mt][n][0], sc[mt][n][1]));
                mx1 = fmaxf(mx1, fmaxf(sc[mt][n][2], sc[mt][n][3]));
            }
            mx0 = fmaxf(mx0, __shfl_xor_sync(0xffffffffu, mx0, 1));
            mx0 = fmaxf(mx0, __shfl_xor_sync(0xffffffffu, mx0, 2));
            mx1 = fmaxf(mx1, __shfl_xor_sync(0xffffffffu, mx1, 1));
            mx1 = fmaxf(mx1, __shfl_xor_sync(0xffffffffu, mx1, 2));
            const float mn0 = fmaxf(mM[mt][0], mx0);
            const float mn1 = fmaxf(mM[mt][1], mx1);
            const float c0 = exp2f(mM[mt][0] - mn0);
            const float c1 = exp2f(mM[mt][1] - mn1);
            mM[mt][0] = mn0; mM[mt][1] = mn1;

            #pragma unroll
            for (int s = 0; s < 4; s++) {
                pa[mt][s][0] = h2exp2(packh2(sc[mt][2*s][0]   - mn0, sc[mt][2*s][1]   - mn0));
                pa[mt][s][1] = h2exp2(packh2(sc[mt][2*s][2]   - mn1, sc[mt][2*s][3]   - mn1));
                pa[mt][s][2] = h2exp2(packh2(sc[mt][2*s+1][0] - mn0, sc[mt][2*s+1][1] - mn0));
                pa[mt][s][3] = h2exp2(packh2(sc[mt][2*s+1][2] - mn1, sc[mt][2*s+1][3] - mn1));
            }

            float lacc[4] = {0.f, 0.f, 0.f, 0.f};
            #pragma unroll
            for (int s = 0; s < 4; s++)
                mma_f16(lacc, pa[mt][s], ONES2, ONES2);
            lL[mt][0] = lL[mt][0] * c0 + lacc[0];
            lL[mt][1] = lL[mt][1] * c1 + lacc[2];

            #pragma unroll
            for (int n = 0; n < 8; n++) {
                o[mt][n][0] *= c0; o[mt][n][1] *= c0;
                o[mt][n][2] *= c1; o[mt][n][3] *= c1;
            }
        }

        #pragma unroll
        for (int mt = 0; mt < 2; mt++)
            #pragma unroll
            for (int n = 0; n < 8; n++)
                mma_f16(o[mt][n], pa[mt][0], vf0[n][0], vf0[n][1]);

        #pragma unroll
        for (int s = 1; s < 4; s++) {
            uint32_t vfr[8][2];
            #pragma unroll
            for (int nt = 0; nt < 4; nt++) {
                const int r = s * 16 + (mi & 1) * 8 + (lane & 7);
                const int c = 2 * nt + (mi >> 1);
                ldsm_x4t(vfr[2*nt][0], vfr[2*nt][1], vfr[2*nt+1][0], vfr[2*nt+1][1],
                         vo + r * 128 + ((c ^ (r & 7)) * 16));
            }
            #pragma unroll
            for (int mt = 0; mt < 2; mt++)
                #pragma unroll
                for (int n = 0; n < 8; n++)
                    mma_f16(o[mt][n], pa[mt][s], vfr[n][0], vfr[n][1]);
        }

        if (kt + 2 < KT) { loadKV(kt + 2); CPCOMMIT(); }
    }

    #pragma unroll
    for (int mt = 0; mt < 2; mt++) {
        const float i0 = 1.f / lL[mt][0], i1 = 1.f / lL[mt][1];
        const int r0 = wrow + mt * 16 + gg;
        const int r1 = r0 + 8;
        #pragma unroll
        for (int n = 0; n < 8; n++) {
            const int col = h * 64 + n * 8 + tg * 2;
            *(uint32_t*)(obuf + (size_t)r0 * D_MODEL + col) =
                packh2(o[mt][n][0] * i0, o[mt][n][1] * i0);
            *(uint32_t*)(obuf + (size_t)r1 * D_MODEL + col) =
                packh2(o[mt][n][2] * i1, o[mt][n][3] * i1);
        }
    }
}

// ---------------------------------------------------------------------------
// fused flash + O-projection.  grid = 768:
//   bid 0..511   : flash, qt = 15 - bid/32 (longest first), h = bid % 32
//   bid 512..767 : O-proj tile; spins until its qt's 32 flash CTAs are done
// ---------------------------------------------------------------------------
__global__ __launch_bounds__(128, 2)
void flash_o(const __half* __restrict__ qbuf, const __half* __restrict__ kbuf,
             const __half* __restrict__ vbuf, __half* __restrict__ abuf,
             const __half* __restrict__ WO, const float* __restrict__ bo,
             float* __restrict__ out)
{
    extern __shared__ char sm[];
    const int bid = blockIdx.x;
    if (bid < 512) {
        const int qt = 15 - (bid >> 5);
        const int h  = bid & 31;
        flash_body(qbuf, kbuf, vbuf, abuf, qt, h, sm);
        __syncthreads();
        if (threadIdx.x == 0) {
            __threadfence();
            atomicAdd(&g_ocnt[qt], 1);
        }
    } else {
        const int t  = bid - 512;
        const int qi = t >> 4;
        const int n0 = (t & 15) * 128;
        if (threadIdx.x == 0) {
            while (atomicAdd(&g_ocnt[qi], 0) < 32)
                __nanosleep(64);
        }
        __syncthreads();
        __threadfence();
        gemm_body<0>(abuf, WO, bo, out, D_MODEL, D_MODEL, qi * 128, n0, smem_u32(sm));
    }
}

// ---------------------------------------------------------------------------
// Launch
// ---------------------------------------------------------------------------
extern "C" void kernel_launch(void* const* d_in, const int* in_sizes, int n_in,
                              void* d_out, int out_size)
{
    const float* queries = (const float*)d_in[0];
    const float* keys    = (const float*)d_in[1];
    const float* values  = (const float*)d_in[2];
    const float* Wq      = (const float*)d_in[3];
    const float* bq      = (const float*)d_in[4];
    const float* Wk      = (const float*)d_in[5];
    const float* bk      = (const float*)d_in[6];
    const float* Wv      = (const float*)d_in[7];
    const float* bv      = (const float*)d_in[8];
    const float* Wo      = (const float*)d_in[9];
    const float* bo      = (const float*)d_in[10];
    float*       out     = (float*)d_out;

    __half *qh, *kh, *vh, *ah, *bh, *ch, *wq, *wk, *wv, *wo;
    cudaGetSymbolAddress((void**)&qh, g_qh);
    cudaGetSymbolAddress((void**)&kh, g_kh);
    cudaGetSymbolAddress((void**)&vh, g_vh);
    cudaGetSymbolAddress((void**)&ah, g_ah);
    cudaGetSymbolAddress((void**)&bh, g_bh);
    cudaGetSymbolAddress((void**)&ch, g_ch);
    cudaGetSymbolAddress((void**)&wq, g_wq);
    cudaGetSymbolAddress((void**)&wk, g_wk);
    cudaGetSymbolAddress((void**)&wv, g_wv);
    cudaGetSymbolAddress((void**)&wo, g_wo);

    cudaFuncSetAttribute(gemm_qkv, cudaFuncAttributeMaxDynamicSharedMemorySize, 3 * GSTAGE);
    cudaFuncSetAttribute(flash_o,  cudaFuncAttributeMaxDynamicSharedMemorySize, 3 * GSTAGE);

    // streaming prep (weights keep [K,N] layout) + counter reset
    prep<<<dim3(64, 64, 7), 256>>>(
        (const float4*)Wq, (const float4*)Wk, (const float4*)Wv, (const float4*)Wo,
        (const float4*)queries, (const float4*)keys, (const float4*)values,
        wq, wk, wv, wo, ah, bh, ch);

    // Q + K + V projections fused
    gemm_qkv<<<dim3(24, S_LEN / 128), 128, 3 * GSTAGE>>>(
        ah, bh, ch, wq, wk, wv, bq, bk, bv, qh, kh, vh);

    // fused: causal GQA flash attention + output projection
    flash_o<<<768, 128, 3 * GSTAGE>>>(qh, kh, vh, ah, wo, bo, out);
}

// round 15
// speedup vs baseline: 1.0869x; 1.0478x over previous
#include <cuda_runtime.h>
#include <cuda_bf16.h>
#include <cuda_fp16.h>
#include <cstdint>

// ===========================================================================
// GQA layer, sm_103 baseline-PTX path: mma.sync (HMMA) everywhere.
//   - prep: pure-streaming fp32->fp16, 4 float4/thread (MLP=4)
//   - gemm_qkv: fused Q/K/V projections (K-major B via ldsm.trans)
//   - flash_o: flash attention + O-projection fused via per-qt counters
// ===========================================================================

#define S_LEN   2048
#define D_MODEL 2048
#define H_Q     32
#define KV_W    512
#define GK      2048
#define QSCALE  0.1803368801111244f   // 0.125 * log2(e)
#define ONES2   0x3C003C00u           // half2(1.0, 1.0)

// ------------------------------ scratch ------------------------------------
__device__ __align__(16) __half g_qh[S_LEN * D_MODEL];
__device__ __align__(16) __half g_kh[S_LEN * KV_W];
__device__ __align__(16) __half g_vh[S_LEN * KV_W];

__device__ __align__(16) __half g_ah[S_LEN * D_MODEL];
__device__ __align__(16) __half g_bh[S_LEN * D_MODEL];
__device__ __align__(16) __half g_ch[S_LEN * D_MODEL];

// weights fp16, native [K][N] layout
__device__ __align__(16) __half g_wq[GK * D_MODEL];
__device__ __align__(16) __half g_wk[GK * KV_W];
__device__ __align__(16) __half g_wv[GK * KV_W];
__device__ __align__(16) __half g_wo[GK * D_MODEL];

__device__ int g_ocnt[16];    // per qt: 32 flash CTAs done

// ------------------------------ helpers ------------------------------------
__device__ __forceinline__ uint32_t smem_u32(const void* p) {
    uint32_t a;
    asm("{ .reg .u64 t; cvta.to.shared.u64 t, %1; cvt.u32.u64 %0, t; }"
        : "=r"(a) : "l"(p));
    return a;
}

#define CP16(dst, src) \
    asm volatile("cp.async.cg.shared.global [%0], [%1], 16;" \
                 :: "r"(dst), "l"(src))
#define CPCOMMIT() asm volatile("cp.async.commit_group;" ::: "memory")
#define CPWAIT(n)  asm volatile("cp.async.wait_group %0;" :: "n"(n) : "memory")

__device__ __forceinline__ void ldsm_x4(uint32_t& r0, uint32_t& r1,
                                        uint32_t& r2, uint32_t& r3, uint32_t a) {
    asm volatile("ldmatrix.sync.aligned.m8n8.x4.shared.b16 {%0,%1,%2,%3}, [%4];"
                 : "=r"(r0), "=r"(r1), "=r"(r2), "=r"(r3) : "r"(a));
}
__device__ __forceinline__ void ldsm_x4t(uint32_t& r0, uint32_t& r1,
                                         uint32_t& r2, uint32_t& r3, uint32_t a) {
    asm volatile("ldmatrix.sync.aligned.m8n8.x4.trans.shared.b16 {%0,%1,%2,%3}, [%4];"
                 : "=r"(r0), "=r"(r1), "=r"(r2), "=r"(r3) : "r"(a));
}

__device__ __forceinline__ void mma_f16(float* c, const uint32_t* a,
                                        uint32_t b0, uint32_t b1) {
    asm volatile("mma.sync.aligned.m16n8k16.row.col.f32.f16.f16.f32 "
                 "{%0,%1,%2,%3}, {%4,%5,%6,%7}, {%8,%9}, {%0,%1,%2,%3};"
                 : "+f"(c[0]), "+f"(c[1]), "+f"(c[2]), "+f"(c[3])
                 : "r"(a[0]), "r"(a[1]), "r"(a[2]), "r"(a[3]), "r"(b0), "r"(b1));
}

__device__ __forceinline__ uint32_t h2exp2(uint32_t x) {
    uint32_t r;
    asm("ex2.approx.f16x2 %0, %1;" : "=r"(r) : "r"(x));
    return r;
}
__device__ __forceinline__ uint32_t packh2(float a, float b) {
    __half2 h = __floats2half2_rn(a, b);
    return *reinterpret_cast<uint32_t*>(&h);
}

// ---------------------------------------------------------------------------
// prep: streaming fp32 -> fp16, 4 float4 per thread (MLP=4).
// grid (64, 16, 7), 256 thr: each CTA converts 1024 consecutive float4s.
// ---------------------------------------------------------------------------
__global__ __launch_bounds__(256)
void prep(const float4* __restrict__ Wq, const float4* __restrict__ Wk,
          const float4* __restrict__ Wv, const float4* __restrict__ Wo,
          const float4* __restrict__ Qa, const float4* __restrict__ Ka,
          const float4* __restrict__ Va,
          __half* __restrict__ wq, __half* __restrict__ wk,
          __half* __restrict__ wv, __half* __restrict__ wo,
          __half* __restrict__ ah, __half* __restrict__ bh,
          __half* __restrict__ ch)
{
    if (blockIdx.x == 0 && blockIdx.y == 0 && blockIdx.z == 0 &&
        threadIdx.x < 16)
        g_ocnt[threadIdx.x] = 0;

    const int z = blockIdx.z;
    const float4* A;  __half* dst;  int n4;
    if      (z == 0) { A = Wq; dst = wq; n4 = GK * D_MODEL / 4; }
    else if (z == 1) { A = Wk; dst = wk; n4 = GK * KV_W / 4; }
    else if (z == 2) { A = Wv; dst = wv; n4 = GK * KV_W / 4; }
    else if (z == 3) { A = Wo; dst = wo; n4 = GK * D_MODEL / 4; }
    else if (z == 4) { A = Qa; dst = ah; n4 = S_LEN * D_MODEL / 4; }
    else if (z == 5) { A = Ka; dst = bh; n4 = S_LEN * D_MODEL / 4; }
    else             { A = Va; dst = ch; n4 = S_LEN * D_MODEL / 4; }

    const int base = (blockIdx.y * 64 + blockIdx.x) * 1024 + threadIdx.x;
    if (base >= n4) return;

    // issue all loads first (MLP=4), then convert+store
    float4 v[4];
    bool ok[4];
    #pragma unroll
    for (int j = 0; j < 4; j++) {
        const int i = base + j * 256;
        ok[j] = (i < n4);
        if (ok[j]) v[j] = A[i];
    }
    #pragma unroll
    for (int j = 0; j < 4; j++) {
        if (!ok[j]) continue;
        const int i = base + j * 256;
        __half2 h0 = __floats2half2_rn(v[j].x, v[j].y);
        __half2 h1 = __floats2half2_rn(v[j].z, v[j].w);
        uint2 u = make_uint2(*(uint32_t*)&h0, *(uint32_t*)&h1);
        *(uint2*)(dst + (size_t)i * 4) = u;
    }
}

// ---------------------------------------------------------------------------
// GEMM body: C[128x128] = A @ B + bias.  A [M][GK] fp16 row-major;
// B [GK][NtotB] fp16 K-major (native weight layout), fragments via ldsm.trans.
// BK=64, 128 thr, 4 warps (2m x 2n), warp tile 64x64, 3-stage, 32KB/stage.
// MODE 0: float out; MODE 1: half out; MODE 2: half out * QSCALE.
// ---------------------------------------------------------------------------
#define GSTAGE 32768

template <int MODE>
__device__ __forceinline__
void gemm_body(const __half* __restrict__ A, const __half* __restrict__ B,
               const float* __restrict__ bias, void* __restrict__ Cout,
               int Ntot, int NtotB, int m0, int n0, uint32_t sb)
{
    const int tid  = threadIdx.x;
    const int lane = tid & 31;
    const int wid  = tid >> 5;
    const int wm   = (wid & 1) * 64;
    const int wn   = (wid >> 1) * 64;
    const int gg   = lane >> 2, tg = lane & 3;
    const int mi   = lane >> 3;
    const uint32_t bsub = sb + 16384 + (wid >> 1) * 8192;

    float acc[4][8][4];
    #pragma unroll
    for (int a = 0; a < 4; a++)
        #pragma unroll
        for (int b = 0; b < 8; b++)
            #pragma unroll
            for (int c = 0; c < 4; c++) acc[a][b][c] = 0.f;

    auto load_stage = [&](int it) {
        const uint32_t st = sb + (it % 3) * GSTAGE;
        const int k0 = it * 64;
        #pragma unroll
        for (int t = 0; t < 8; t++) {
            const int f   = tid + t * 128;
            const int row = f >> 3, c = f & 7;
            CP16(st + row * 128 + ((c ^ (row & 7)) * 16),
                 A + (size_t)(m0 + row) * GK + k0 + c * 8);
        }
        #pragma unroll
        for (int t = 0; t < 8; t++) {
            const int f   = tid + t * 128;
            const int sub = f >> 9;
            const int rem = f & 511;
            const int row = rem >> 3, c = rem & 7;
            CP16(st + 16384 + sub * 8192 + row * 128 + ((c ^ (row & 7)) * 16),
                 B + (size_t)(k0 + row) * NtotB + n0 + sub * 64 + c * 8);
        }
    };

    load_stage(0); CPCOMMIT();
    load_stage(1); CPCOMMIT();

    const int NIT = GK / 64;
    for (int it = 0; it < NIT; it++) {
        if (it + 1 < NIT) { CPWAIT(1); } else { CPWAIT(0); }
        __syncthreads();
        const uint32_t st  = sb + (it % 3) * GSTAGE;
        const uint32_t bst = bsub + (it % 3) * GSTAGE;

        #pragma unroll
        for (int s = 0; s < 4; s++) {
            uint32_t aF[4][4];
            #pragma unroll
            for (int mt = 0; mt < 4; mt++) {
                const int r = wm + mt * 16 + (mi & 1) * 8 + (lane & 7);
                const int c = 2 * s + (mi >> 1);
                ldsm_x4(aF[mt][0], aF[mt][1], aF[mt][2], aF[mt][3],
                        st + r * 128 + ((c ^ (r & 7)) * 16));
            }
            uint32_t bF[8][2];
            #pragma unroll
            for (int nt = 0; nt < 4; nt++) {
                const int r = s * 16 + (mi & 1) * 8 + (lane & 7);
                const int c = 2 * nt + (mi >> 1);
                ldsm_x4t(bF[2*nt][0], bF[2*nt][1], bF[2*nt+1][0], bF[2*nt+1][1],
                         bst + r * 128 + ((c ^ (r & 7)) * 16));
            }
            #pragma unroll
            for (int mt = 0; mt < 4; mt++)
                #pragma unroll
                for (int n = 0; n < 8; n++)
                    mma_f16(acc[mt][n], aF[mt], bF[n][0], bF[n][1]);
        }
        if (it + 2 < NIT) { load_stage(it + 2); CPCOMMIT(); }
    }

    #pragma unroll
    for (int mt = 0; mt < 4; mt++)
        #pragma unroll
        for (int n = 0; n < 8; n++) {
            const int r0  = m0 + wm + mt * 16 + gg;
            const int col = n0 + wn + n * 8 + tg * 2;
            const float b0 = bias[col], b1 = bias[col + 1];
            if (MODE == 0) {
                float* C = (float*)Cout;
                *(float2*)(C + (size_t)r0 * Ntot + col) =
                    make_float2(acc[mt][n][0] + b0, acc[mt][n][1] + b1);
                *(float2*)(C + (size_t)(r0 + 8) * Ntot + col) =
                    make_float2(acc[mt][n][2] + b0, acc[mt][n][3] + b1);
            } else {
                const float sc = (MODE == 2) ? QSCALE : 1.0f;
                __half* C = (__half*)Cout;
                __half2 h0 = __floats2half2_rn((acc[mt][n][0] + b0) * sc,
                                               (acc[mt][n][1] + b1) * sc);
                __half2 h1 = __floats2half2_rn((acc[mt][n][2] + b0) * sc,
                                               (acc[mt][n][3] + b1) * sc);
                *(__half2*)(C + (size_t)r0 * Ntot + col) = h0;
                *(__half2*)(C + (size_t)(r0 + 8) * Ntot + col) = h1;
            }
        }
}

// fused Q + K + V projections: grid (24, 16)
__global__ __launch_bounds__(128, 2)
void gemm_qkv(const __half* __restrict__ Qa, const __half* __restrict__ Ka,
              const __half* __restrict__ Va,
              const __half* __restrict__ WQ, const __half* __restrict__ WK,
              const __half* __restrict__ WV,
              const float* __restrict__ bq, const float* __restrict__ bk,
              const float* __restrict__ bv,
              __half* __restrict__ qh, __half* __restrict__ kh, __half* __restrict__ vh)
{
    extern __shared__ char sm[];
    const uint32_t sb = smem_u32(sm);
    const int bx = blockIdx.x;
    const int m0 = blockIdx.y * 128;
    if (bx < 16)
        gemm_body<2>(Qa, WQ, bq, qh, D_MODEL, D_MODEL, m0, bx * 128, sb);
    else if (bx < 20)
        gemm_body<1>(Ka, WK, bk, kh, KV_W, KV_W, m0, (bx - 16) * 128, sb);
    else
        gemm_body<1>(Va, WV, bv, vh, KV_W, KV_W, m0, (bx - 20) * 128, sb);
}

// ---------------------------------------------------------------------------
// flash body (math identical to R12/R14)
// ---------------------------------------------------------------------------
__device__ __forceinline__
void flash_body(const __half* __restrict__ qbuf, const __half* __restrict__ kbuf,
                const __half* __restrict__ vbuf, __half* __restrict__ obuf,
                int qt, int h, char* smem)
{
    const uint32_t qb  = smem_u32(smem);
    const uint32_t kb0 = qb + 16384;
    const uint32_t vb0 = qb + 40960;

    const int g    = h >> 2;
    const int tid  = threadIdx.x;
    const int warp = tid >> 5, lane = tid & 31;
    const int gg   = lane >> 2, tg = lane & 3;
    const int mi   = lane >> 3;
    const int q0   = qt * 128;
    const int wrow = q0 + warp * 32;

    #pragma unroll
    for (int i = 0; i < 8; i++) {
        const int f = tid + i * 128;
        const int r = f >> 3, c = f & 7;
        CP16(qb + r * 128 + ((c ^ (r & 7)) * 16),
             qbuf + (size_t)(q0 + r) * D_MODEL + h * 64 + c * 8);
    }
    auto loadKV = [&](int kt) {
        const uint32_t ko = kb0 + (kt % 3) * 8192;
        const uint32_t vo = vb0 + (kt % 3) * 8192;
        #pragma unroll
        for (int i = 0; i < 4; i++) {
            const int f = tid + i * 128;
            const int r = f >> 3, c = f & 7;
            const size_t src = (size_t)(kt * 64 + r) * KV_W + g * 64 + c * 8;
            const uint32_t d = r * 128 + ((c ^ (r & 7)) * 16);
            CP16(ko + d, kbuf + src);
            CP16(vo + d, vbuf + src);
        }
    };
    const int KT = 2 * qt + 2;
    loadKV(0); CPCOMMIT();
    if (KT > 1) loadKV(1);
    CPCOMMIT();
    CPWAIT(1);
    __syncthreads();

    uint32_t qa[4][2][4];
    #pragma unroll
    for (int mt = 0; mt < 2; mt++) {
        const int r = warp * 32 + mt * 16 + (mi & 1) * 8 + (lane & 7);
        #pragma unroll
        for (int s = 0; s < 4; s++) {
            const int c = 2 * s + (mi >> 1);
            ldsm_x4(qa[s][mt][0], qa[s][mt][1], qa[s][mt][2], qa[s][mt][3],
                    qb + r * 128 + ((c ^ (r & 7)) * 16));
        }
    }

    float o[2][8][4];
    #pragma unroll
    for (int mt = 0; mt < 2; mt++)
        #pragma unroll
        for (int n = 0; n < 8; n++)
            #pragma unroll
            for (int c = 0; c < 4; c++) o[mt][n][c] = 0.f;
    float mM[2][2] = {{-1e30f, -1e30f}, {-1e30f, -1e30f}};
    float lL[2][2] = {{0.f, 0.f}, {0.f, 0.f}};

    for (int kt = 0; kt < KT; kt++) {
        if (kt > 0) {
            if (kt + 1 < KT) { CPWAIT(1); } else { CPWAIT(0); }
            __syncthreads();
        }
        const uint32_t ko = kb0 + (kt % 3) * 8192;
        const uint32_t vo = vb0 + (kt % 3) * 8192;

        float sc[2][8][4];
        #pragma unroll
        for (int mt = 0; mt < 2; mt++)
            #pragma unroll
            for (int n = 0; n < 8; n++)
                #pragma unroll
                for (int c = 0; c < 4; c++) sc[mt][n][c] = 0.f;

        #pragma unroll
        for (int s = 0; s < 4; s++) {
            uint32_t bfr[8][2];
            #pragma unroll
            for (int nt = 0; nt < 4; nt++) {
                const int r = nt * 16 + (mi >> 1) * 8 + (lane & 7);
                const int c = 2 * s + (mi & 1);
                ldsm_x4(bfr[2*nt][0], bfr[2*nt][1], bfr[2*nt+1][0], bfr[2*nt+1][1],
                        ko + r * 128 + ((c ^ (r & 7)) * 16));
            }
            #pragma unroll
            for (int mt = 0; mt < 2; mt++)
                #pragma unroll
                for (int n = 0; n < 8; n++)
                    mma_f16(sc[mt][n], qa[s][mt], bfr[n][0], bfr[n][1]);
        }

        uint32_t vf0[8][2];
        #pragma unroll
        for (int nt = 0; nt < 4; nt++) {
            const int r = (mi & 1) * 8 + (lane & 7);
            const int c = 2 * nt + (mi >> 1);
            ldsm_x4t(vf0[2*nt][0], vf0[2*nt][1], vf0[2*nt+1][0], vf0[2*nt+1][1],
                     vo + r * 128 + ((c ^ (r & 7)) * 16));
        }

        if (kt * 64 + 63 > wrow) {
            #pragma unroll
            for (int mt = 0; mt < 2; mt++) {
                const int r0 = wrow + mt * 16 + gg;
                const int r1 = r0 + 8;
                #pragma unroll
                for (int n = 0; n < 8; n++) {
                    const int col = kt * 64 + n * 8 + tg * 2;
                    if (col     > r0) sc[mt][n][0] = -1e30f;
                    if (col + 1 > r0) sc[mt][n][1] = -1e30f;
                    if (col     > r1) sc[mt][n][2] = -1e30f;
                    if (col + 1 > r1) sc[mt][n][3] = -1e30f;
                }
            }
        }

        uint32_t pa[2][4][4];
        #pragma unroll
        for (int mt = 0; mt < 2; mt++) {
            float mx0 = -1e30f, mx1 = -1e30f;
            #pragma unroll
            for (int n = 0; n < 8; n++) {
                mx0 = fmaxf(mx0, fmaxf(sc[mt][n][0], sc[mt][n][1]));
                mx1 = fmaxf(mx1, fmaxf(sc[mt][n][2], sc[mt][n][3]));
            }
            mx0 = fmaxf(mx0, __shfl_xor_sync(0xffffffffu, mx0, 1));
            mx0 = fmaxf(mx0, __shfl_xor_sync(0xffffffffu, mx0, 2));
            mx1 = fmaxf(mx1, __shfl_xor_sync(0xffffffffu, mx1, 1));
            mx1 = fmaxf(mx1, __shfl_xor_sync(0xffffffffu, mx1, 2));
            const float mn0 = fmaxf(mM[mt][0], mx0);
            const float mn1 = fmaxf(mM[mt][1], mx1);
            const float c0 = exp2f(mM[mt][0] - mn0);
            const float c1 = exp2f(mM[mt][1] - mn1);
            mM[mt][0] = mn0; mM[mt][1] = mn1;

            #pragma unroll
            for (int s = 0; s < 4; s++) {
                pa[mt][s][0] = h2exp2(packh2(sc[mt][2*s][0]   - mn0, sc[mt][2*s][1]   - mn0));
                pa[mt][s][1] = h2exp2(packh2(sc[mt][2*s][2]   - mn1, sc[mt][2*s][3]   - mn1));
                pa[mt][s][2] = h2exp2(packh2(sc[mt][2*s+1][0] - mn0, sc[mt][2*s+1][1] - mn0));
                pa[mt][s][3] = h2exp2(packh2(sc[mt][2*s+1][2] - mn1, sc[mt][2*s+1][3] - mn1));
            }

            float lacc[4] = {0.f, 0.f, 0.f, 0.f};
            #pragma unroll
            for (int s = 0; s < 4; s++)
                mma_f16(lacc, pa[mt][s], ONES2, ONES2);
            lL[mt][0] = lL[mt][0] * c0 + lacc[0];
            lL[mt][1] = lL[mt][1] * c1 + lacc[2];

            #pragma unroll
            for (int n = 0; n < 8; n++) {
                o[mt][n][0] *= c0; o[mt][n][1] *= c0;
                o[mt][n][2] *= c1; o[mt][n][3] *= c1;
            }
        }

        #pragma unroll
        for (int mt = 0; mt < 2; mt++)
            #pragma unroll
            for (int n = 0; n < 8; n++)
                mma_f16(o[mt][n], pa[mt][0], vf0[n][0], vf0[n][1]);

        #pragma unroll
        for (int s = 1; s < 4; s++) {
            uint32_t vfr[8][2];
            #pragma unroll
            for (int nt = 0; nt < 4; nt++) {
                const int r = s * 16 + (mi & 1) * 8 + (lane & 7);
                const int c = 2 * nt + (mi >> 1);
                ldsm_x4t(vfr[2*nt][0], vfr[2*nt][1], vfr[2*nt+1][0], vfr[2*nt+1][1],
                         vo + r * 128 + ((c ^ (r & 7)) * 16));
            }
            #pragma unroll
            for (int mt = 0; mt < 2; mt++)
                #pragma unroll
                for (int n = 0; n < 8; n++)
                    mma_f16(o[mt][n], pa[mt][s], vfr[n][0], vfr[n][1]);
        }

        if (kt + 2 < KT) { loadKV(kt + 2); CPCOMMIT(); }
    }

    #pragma unroll
    for (int mt = 0; mt < 2; mt++) {
        const float i0 = 1.f / lL[mt][0], i1 = 1.f / lL[mt][1];
        const int r0 = wrow + mt * 16 + gg;
        const int r1 = r0 + 8;
        #pragma unroll
        for (int n = 0; n < 8; n++) {
            const int col = h * 64 + n * 8 + tg * 2;
            *(uint32_t*)(obuf + (size_t)r0 * D_MODEL + col) =
                packh2(o[mt][n][0] * i0, o[mt][n][1] * i0);
            *(uint32_t*)(obuf + (size_t)r1 * D_MODEL + col) =
                packh2(o[mt][n][2] * i1, o[mt][n][3] * i1);
        }
    }
}

// ---------------------------------------------------------------------------
// fused flash + O-projection.  grid = 768:
//   bid 0..511   : flash, qt = 15 - bid/32 (longest first), h = bid % 32
//   bid 512..767 : O-proj tile; spins until its qt's 32 flash CTAs are done
// ---------------------------------------------------------------------------
__global__ __launch_bounds__(128, 2)
void flash_o(const __half* __restrict__ qbuf, const __half* __restrict__ kbuf,
             const __half* __restrict__ vbuf, __half* __restrict__ abuf,
             const __half* __restrict__ WO, const float* __restrict__ bo,
             float* __restrict__ out)
{
    extern __shared__ char sm[];
    const int bid = blockIdx.x;
    if (bid < 512) {
        const int qt = 15 - (bid >> 5);
        const int h  = bid & 31;
        flash_body(qbuf, kbuf, vbuf, abuf, qt, h, sm);
        __syncthreads();
        if (threadIdx.x == 0) {
            __threadfence();
            atomicAdd(&g_ocnt[qt], 1);
        }
    } else {
        const int t  = bid - 512;
        const int qi = t >> 4;
        const int n0 = (t & 15) * 128;
        if (threadIdx.x == 0) {
            while (atomicAdd(&g_ocnt[qi], 0) < 32)
                __nanosleep(64);
        }
        __syncthreads();
        __threadfence();
        gemm_body<0>(abuf, WO, bo, out, D_MODEL, D_MODEL, qi * 128, n0, smem_u32(sm));
    }
}

// ---------------------------------------------------------------------------
// Launch
// ---------------------------------------------------------------------------
extern "C" void kernel_launch(void* const* d_in, const int* in_sizes, int n_in,
                              void* d_out, int out_size)
{
    const float* queries = (const float*)d_in[0];
    const float* keys    = (const float*)d_in[1];
    const float* values  = (const float*)d_in[2];
    const float* Wq      = (const float*)d_in[3];
    const float* bq      = (const float*)d_in[4];
    const float* Wk      = (const float*)d_in[5];
    const float* bk      = (const float*)d_in[6];
    const float* Wv      = (const float*)d_in[7];
    const float* bv      = (const float*)d_in[8];
    const float* Wo      = (const float*)d_in[9];
    const float* bo      = (const float*)d_in[10];
    float*       out     = (float*)d_out;

    __half *qh, *kh, *vh, *ah, *bh, *ch, *wq, *wk, *wv, *wo;
    cudaGetSymbolAddress((void**)&qh, g_qh);
    cudaGetSymbolAddress((void**)&kh, g_kh);
    cudaGetSymbolAddress((void**)&vh, g_vh);
    cudaGetSymbolAddress((void**)&ah, g_ah);
    cudaGetSymbolAddress((void**)&bh, g_bh);
    cudaGetSymbolAddress((void**)&ch, g_ch);
    cudaGetSymbolAddress((void**)&wq, g_wq);
    cudaGetSymbolAddress((void**)&wk, g_wk);
    cudaGetSymbolAddress((void**)&wv, g_wv);
    cudaGetSymbolAddress((void**)&wo, g_wo);

    cudaFuncSetAttribute(gemm_qkv, cudaFuncAttributeMaxDynamicSharedMemorySize, 3 * GSTAGE);
    cudaFuncSetAttribute(flash_o,  cudaFuncAttributeMaxDynamicSharedMemorySize, 3 * GSTAGE);

    // streaming prep (4 float4 / thread) + counter reset
    prep<<<dim3(64, 16, 7), 256>>>(
        (const float4*)Wq, (const float4*)Wk, (const float4*)Wv, (const float4*)Wo,
        (const float4*)queries, (const float4*)keys, (const float4*)values,
        wq, wk, wv, wo, ah, bh, ch);

    // Q + K + V projections fused
    gemm_qkv<<<dim3(24, S_LEN / 128), 128, 3 * GSTAGE>>>(
        ah, bh, ch, wq, wk, wv, bq, bk, bv, qh, kh, vh);

    // fused: causal GQA flash attention + output projection
    flash_o<<<768, 128, 3 * GSTAGE>>>(qh, kh, vh, ah, wo, bo, out);
}